// round 13
// baseline (speedup 1.0000x reference)
#include <cuda_runtime.h>
#include <cuda_fp16.h>
#include <math.h>
#include <stdint.h>

#define NN    8192
#define DIMM  512
#define DKK   128
#define DVV   512
#define NCHUNK 256
#define CHUNK  32

// ---------------- scratch (device globals; no allocation) ----------------
__device__ float  g_u1[DIMM], g_u2[DIMM];
__device__ double g_beta[2];
__device__ float  g_s[NN], g_d[NN];
__device__ uint32_t g_Dbits;
__device__ int    g_rank[NN];
__device__ unsigned long long g_key[NN];
__device__ float  g_sorted[NN];
__device__ float  g_w1[NN], g_w2[NN];
__device__ float  g_Vs[(size_t)NN * DVV];
__device__ float  g_P1[(size_t)(NN + 1) * DVV];
__device__ float  g_P2[(size_t)(NN + 1) * DVV];
__device__ float  g_zp1[NN + 1], g_zp2[NN + 1];
__device__ float  g_aggA1[(size_t)NCHUNK * DVV], g_aggA2[(size_t)NCHUNK * DVV];
__device__ float  g_incA1[(size_t)NCHUNK * DVV], g_incA2[(size_t)NCHUNK * DVV];
__device__ float  g_aggW[NCHUNK][2], g_incW[NCHUNK][2];
__device__ int    g_status[NCHUNK];
__device__ __half g_Xh[(size_t)NN * DIMM];
__device__ __half g_Wh[(size_t)DVV * DIMM];

// ---------------- helpers ----------------
__device__ __forceinline__ uint32_t smem_u32(const void* p) {
    uint32_t a;
    asm("{ .reg .u64 t; cvta.to.shared.u64 t, %1; cvt.u32.u64 %0, t; }" : "=r"(a) : "l"(p));
    return a;
}
__device__ __forceinline__ void cp16(uint32_t saddr, const void* gaddr) {
    asm volatile("cp.async.cg.shared.global [%0], [%1], 16;" :: "r"(saddr), "l"(gaddr) : "memory");
}
#define CP_COMMIT() asm volatile("cp.async.commit_group;" ::: "memory")
#define CP_WAIT(n)  asm volatile("cp.async.wait_group %0;" :: "n"(n) : "memory")

__device__ __forceinline__ void ldsm_x4(uint32_t& r0, uint32_t& r1, uint32_t& r2, uint32_t& r3,
                                        uint32_t addr) {
    asm volatile("ldmatrix.sync.aligned.m8n8.x4.shared.b16 {%0,%1,%2,%3}, [%4];"
                 : "=r"(r0), "=r"(r1), "=r"(r2), "=r"(r3) : "r"(addr));
}
__device__ __forceinline__ void mma16816(float* c, uint32_t a0, uint32_t a1, uint32_t a2,
                                         uint32_t a3, uint32_t b0, uint32_t b1) {
    asm volatile("mma.sync.aligned.m16n8k16.row.col.f32.f16.f16.f32 "
                 "{%0,%1,%2,%3}, {%4,%5,%6,%7}, {%8,%9}, {%0,%1,%2,%3};"
                 : "+f"(c[0]), "+f"(c[1]), "+f"(c[2]), "+f"(c[3])
                 : "r"(a0), "r"(a1), "r"(a2), "r"(a3), "r"(b0), "r"(b1));
}
__device__ __forceinline__ float decode_D() {
    uint32_t u = g_Dbits;
    uint32_t s = (u & 0x80000000u) ? (u ^ 0x80000000u) : ~u;
    return __uint_as_float(s);
}

// ---------------- K0: u1/u2 (4-way ILP), parallel betas; resets ----------------
__global__ void k_prep(const float* __restrict__ Ww, const float* __restrict__ wb,
                       const float* __restrict__ a) {
    int d = blockIdx.x * 256 + threadIdx.x;
    double p0 = 0.0, p1 = 0.0, p2 = 0.0, p3 = 0.0;
    double q0 = 0.0, q1 = 0.0, q2 = 0.0, q3 = 0.0;
    for (int k = 0; k < DKK; k += 4) {
        double w0 = Ww[(size_t)(k + 0) * DIMM + d];
        double w1 = Ww[(size_t)(k + 1) * DIMM + d];
        double w2 = Ww[(size_t)(k + 2) * DIMM + d];
        double w3 = Ww[(size_t)(k + 3) * DIMM + d];
        p0 += w0 * (double)a[k + 0]; p1 += w1 * (double)a[k + 1];
        p2 += w2 * (double)a[k + 2]; p3 += w3 * (double)a[k + 3];
        q0 += w0 * (double)a[DKK + k + 0]; q1 += w1 * (double)a[DKK + k + 1];
        q2 += w2 * (double)a[DKK + k + 2]; q3 += w3 * (double)a[DKK + k + 3];
    }
    g_u1[d] = (float)((p0 + p1) + (p2 + p3));
    g_u2[d] = (float)((q0 + q1) + (q2 + q3));
    if (blockIdx.x == 0) g_status[threadIdx.x] = 0;
    if (blockIdx.x == 0 && threadIdx.x < 32) {
        int lane = threadIdx.x;
        double b1 = 0.0, b2 = 0.0;
        for (int k = lane; k < DKK; k += 32) {
            double w = (double)wb[k];
            b1 += w * (double)a[k];
            b2 += w * (double)a[DKK + k];
        }
        for (int o = 16; o; o >>= 1) {
            b1 += __shfl_down_sync(0xffffffffu, b1, o);
            b2 += __shfl_down_sync(0xffffffffu, b2, o);
        }
        if (lane == 0) {
            g_beta[0] = b1; g_beta[1] = b2;
            g_Dbits = 0u;
        }
    }
}

// ---------------- K1: e_src/e_dst + keys + max(d) + fp16 conversion (fused) -------
__global__ void k_edot(const float* __restrict__ X, const float* __restrict__ Wv) {
    if (blockIdx.x >= NN / 8) {
        int idx = (blockIdx.x - NN / 8) * 256 + threadIdx.x;
        float4 v = ((const float4*)Wv)[idx];
        __half2* pw = (__half2*)g_Wh;
        pw[idx * 2]     = __floats2half2_rn(v.x, v.y);
        pw[idx * 2 + 1] = __floats2half2_rn(v.z, v.w);
        return;
    }
    int warp = (blockIdx.x * blockDim.x + threadIdx.x) >> 5;
    int lane = threadIdx.x & 31;
    const float4* xr = (const float4*)(X + (size_t)warp * DIMM);
    const float4* u1 = (const float4*)g_u1;
    const float4* u2 = (const float4*)g_u2;
    __half2* dxh = (__half2*)(g_Xh + (size_t)warp * DIMM);
    float a1 = 0.f, a2 = 0.f;
#pragma unroll
    for (int i = 0; i < 4; i++) {
        int p = lane + 32 * i;
        float4 xv = xr[p], v1 = u1[p], v2 = u2[p];
        a1 += xv.x * v1.x + xv.y * v1.y + xv.z * v1.z + xv.w * v1.w;
        a2 += xv.x * v2.x + xv.y * v2.y + xv.z * v2.z + xv.w * v2.w;
        dxh[2 * p]     = __floats2half2_rn(xv.x, xv.y);
        dxh[2 * p + 1] = __floats2half2_rn(xv.z, xv.w);
    }
    for (int o = 16; o; o >>= 1) {
        a1 += __shfl_down_sync(0xffffffffu, a1, o);
        a2 += __shfl_down_sync(0xffffffffu, a2, o);
    }
    if (lane == 0) {
        float dv = (float)((double)a2 + g_beta[1]);
        g_s[warp] = (float)((double)a1 + g_beta[0]);
        g_d[warp] = dv;
        g_rank[warp] = 0;
        uint32_t u = __float_as_uint(dv);
        u ^= (uint32_t)(((int32_t)u >> 31)) | 0x80000000u;
        g_key[warp] = ((unsigned long long)u << 13) | (unsigned long long)warp;
        atomicMax(&g_Dbits, u);
    }
}

// ---------------- K2: ranks via u64 key compares (tile 256, 4 j/thread) ----------------
__global__ void k_rank() {
    __shared__ unsigned long long ks[256];
    int t = threadIdx.x;
    ks[t] = g_key[blockIdx.y * 256 + t];
    __syncthreads();
    int j0 = blockIdx.x * 1024 + t;
    unsigned long long k0 = g_key[j0], k1 = g_key[j0 + 256];
    unsigned long long k2 = g_key[j0 + 512], k3 = g_key[j0 + 768];
    int c0 = 0, c1 = 0, c2 = 0, c3 = 0;
#pragma unroll 8
    for (int i = 0; i < 256; i++) {
        unsigned long long kk = ks[i];
        c0 += (kk < k0); c1 += (kk < k1);
        c2 += (kk < k2); c3 += (kk < k3);
    }
    atomicAdd(&g_rank[j0], c0);
    atomicAdd(&g_rank[j0 + 256], c1);
    atomicAdd(&g_rank[j0 + 512], c2);
    atomicAdd(&g_rank[j0 + 768], c3);
}

// ---------------- K3: warp-MMA V GEMM (fp16, 128x256 tile, 3-stage) + scatterd ----
#define KT 64
#define A_TILE (128 * 128)
#define B_TILE (256 * 128)
#define STAGE  (A_TILE + B_TILE)
#define SMEM_VG_BYTES (3 * STAGE)    // 144 KB

__device__ __forceinline__ uint32_t swz(uint32_t row, uint32_t colb) {
    return row * 128u + (colb ^ ((row & 7u) << 4));
}

__global__ void __launch_bounds__(512)
k_vgemm_mma(const float* __restrict__ bv) {
    extern __shared__ char smem[];
    uint32_t sb = smem_u32(smem);
    const int tid = threadIdx.x;
    const int wid = tid >> 5, lane = tid & 31;
    const int wm = wid & 3, wn = wid >> 2;
    const int m0 = blockIdx.y * 128, n0 = blockIdx.x * 256;

    if (blockIdx.x == 0 && tid < 128) {
        int j = m0 + tid;
        int r = g_rank[j];
        float dj = g_d[j];
        float D = decode_D();
        g_sorted[r] = dj;
        g_w1[r] = expf(dj - D);
        g_w2[r] = expf(0.01f * dj);
    }

    const uint32_t sA[3] = { sb, sb + STAGE, sb + 2 * STAGE };
    const uint32_t sB[3] = { sb + A_TILE, sb + STAGE + A_TILE, sb + 2 * STAGE + A_TILE };

    float acc[2][8][4];
#pragma unroll
    for (int i = 0; i < 2; i++)
#pragma unroll
        for (int j = 0; j < 8; j++)
#pragma unroll
            for (int q = 0; q < 4; q++) acc[i][j][q] = 0.f;

    const int arow = tid >> 2, ach0 = (tid & 3) * 2;
    const int brow = tid >> 1, bch0 = (tid & 1) * 4;

    auto issue = [&](int it, int buf) {
        int k0 = it * KT;
        const __half* ga = g_Xh + (size_t)(m0 + arow) * DIMM + k0;
        const __half* gb = g_Wh + (size_t)(n0 + brow) * DIMM + k0;
#pragma unroll
        for (int c = 0; c < 2; c++) {
            int ch = ach0 + c;
            cp16(sA[buf] + swz(arow, ch * 16), ga + ch * 8);
        }
#pragma unroll
        for (int c = 0; c < 4; c++) {
            int ch = bch0 + c;
            cp16(sB[buf] + swz(brow, ch * 16), gb + ch * 8);
        }
    };

    issue(0, 0); CP_COMMIT();
    issue(1, 1); CP_COMMIT();

    int buf = 0;
    for (int it = 0; it < 8; it++) {
        if (it < 7) { CP_WAIT(1); } else { CP_WAIT(0); }
        __syncthreads();

#pragma unroll
        for (int ks = 0; ks < 4; ks++) {
            uint32_t colb = ks * 32 + ((lane >> 4) << 4);
            uint32_t af[2][4];
#pragma unroll
            for (int mt = 0; mt < 2; mt++) {
                uint32_t row = wm * 32 + mt * 16 + (lane & 15);
                ldsm_x4(af[mt][0], af[mt][1], af[mt][2], af[mt][3], sA[buf] + swz(row, colb));
            }
            uint32_t bf[4][4];
#pragma unroll
            for (int np = 0; np < 4; np++) {
                uint32_t row = wn * 64 + np * 16 + (lane & 15);
                ldsm_x4(bf[np][0], bf[np][1], bf[np][2], bf[np][3], sB[buf] + swz(row, colb));
            }
#pragma unroll
            for (int mt = 0; mt < 2; mt++)
#pragma unroll
                for (int nt = 0; nt < 8; nt++) {
                    int np = nt >> 1, sel = nt & 1;
                    mma16816(acc[mt][nt], af[mt][0], af[mt][1], af[mt][2], af[mt][3],
                             bf[np][0 + sel], bf[np][2 + sel]);
                }
        }

        if (it < 6) {
            issue(it + 2, (it + 2) % 3);
            CP_COMMIT();
        }
        buf = (buf + 1) % 3;
    }

    const int g = lane >> 2, tg = lane & 3;
#pragma unroll
    for (int mt = 0; mt < 2; mt++) {
        int j0 = m0 + wm * 32 + mt * 16 + g;
        int j1 = j0 + 8;
        int r0 = g_rank[j0], r1 = g_rank[j1];
        float* d0 = g_Vs + (size_t)r0 * DVV;
        float* d1 = g_Vs + (size_t)r1 * DVV;
#pragma unroll
        for (int nt = 0; nt < 8; nt++) {
            int col = n0 + wn * 64 + nt * 8 + 2 * tg;
            float2 bb = *(const float2*)(bv + col);
            float2 o0 = make_float2(acc[mt][nt][0] + bb.x, acc[mt][nt][1] + bb.y);
            float2 o1 = make_float2(acc[mt][nt][2] + bb.x, acc[mt][nt][3] + bb.y);
            *(float2*)(d0 + col) = o0;
            *(float2*)(d1 + col) = o1;
        }
    }
}

// ---------------- K4: single-pass decoupled-lookback scan (R8 original) ----------
__global__ void __launch_bounds__(256)
k_scanlb() {
    __shared__ int s_p, s_type;
    __shared__ float s_excw1, s_excw2;
    __shared__ float sw1a[CHUNK], sw2a[CHUNK];
    int c = blockIdx.x, t = threadIdx.x;
    int r0 = c * CHUNK;
    int col = 2 * t;

    if (t < CHUNK) { sw1a[t] = g_w1[r0 + t]; sw2a[t] = g_w2[r0 + t]; }
    if (t == 0) { s_excw1 = 0.f; s_excw2 = 0.f; }
    __syncthreads();

    float2 vv[CHUNK];
    float2 a1 = make_float2(0.f, 0.f), a2 = make_float2(0.f, 0.f);
#pragma unroll 4
    for (int r = 0; r < CHUNK; r++) {
        float w1 = sw1a[r], w2 = sw2a[r];
        float2 v = *(const float2*)(g_Vs + (size_t)(r0 + r) * DVV + col);
        vv[r] = v;
        a1.x += w1 * v.x; a1.y += w1 * v.y;
        a2.x += w2 * v.x; a2.y += w2 * v.y;
    }
    *(float2*)(g_aggA1 + (size_t)c * DVV + col) = a1;
    *(float2*)(g_aggA2 + (size_t)c * DVV + col) = a2;
    float lw1 = 0.f, lw2 = 0.f;
    if (t == 0) {
        for (int r = 0; r < CHUNK; r++) { lw1 += sw1a[r]; lw2 += sw2a[r]; }
        g_aggW[c][0] = lw1; g_aggW[c][1] = lw2;
    }
    __threadfence();
    __syncthreads();
    if (t == 0) atomicExch(&g_status[c], 1);

    float2 e1 = make_float2(0.f, 0.f), e2 = make_float2(0.f, 0.f);
    if (c > 0) {
        int p = c - 1;
        while (true) {
            if (t == 0) {
                int st;
                do { st = atomicAdd(&g_status[p], 0); } while (st == 0);
                s_type = st; s_p = p;
            }
            __syncthreads();
            int type = s_type, pp = s_p;
            __threadfence();
            const float* b1 = (type == 2 ? g_incA1 : g_aggA1) + (size_t)pp * DVV;
            const float* b2 = (type == 2 ? g_incA2 : g_aggA2) + (size_t)pp * DVV;
            float2 x1 = *(const float2*)(b1 + col);
            float2 x2 = *(const float2*)(b2 + col);
            e1.x += x1.x; e1.y += x1.y;
            e2.x += x2.x; e2.y += x2.y;
            if (t == 0) {
                const float* w = (type == 2 ? g_incW[pp] : g_aggW[pp]);
                s_excw1 += w[0]; s_excw2 += w[1];
            }
            if (type == 2 || pp == 0) break;
            p = pp - 1;
            __syncthreads();
        }
    }
    __syncthreads();

    *(float2*)(g_incA1 + (size_t)c * DVV + col) = make_float2(e1.x + a1.x, e1.y + a1.y);
    *(float2*)(g_incA2 + (size_t)c * DVV + col) = make_float2(e2.x + a2.x, e2.y + a2.y);
    if (t == 0) {
        g_incW[c][0] = s_excw1 + lw1;
        g_incW[c][1] = s_excw2 + lw2;
    }
    __threadfence();
    __syncthreads();
    if (t == 0) atomicExch(&g_status[c], 2);

    float2 run1 = e1, run2 = e2;
#pragma unroll 4
    for (int r = 0; r < CHUNK; r++) {
        *(float2*)(g_P1 + (size_t)(r0 + r) * DVV + col) = run1;
        *(float2*)(g_P2 + (size_t)(r0 + r) * DVV + col) = run2;
        float w1 = sw1a[r], w2 = sw2a[r];
        float2 v = vv[r];
        run1.x += w1 * v.x; run1.y += w1 * v.y;
        run2.x += w2 * v.x; run2.y += w2 * v.y;
    }
    if (c == NCHUNK - 1) {
        *(float2*)(g_P1 + (size_t)NN * DVV + col) = run1;
        *(float2*)(g_P2 + (size_t)NN * DVV + col) = run2;
    }
    if (t == 0) {
        float z1 = s_excw1, z2 = s_excw2;
        for (int r = 0; r < CHUNK; r++) {
            g_zp1[r0 + r] = z1; g_zp2[r0 + r] = z2;
            z1 += sw1a[r]; z2 += sw2a[r];
        }
        if (c == NCHUNK - 1) { g_zp1[NN] = z1; g_zp2[NN] = z2; }
    }
}

// ---------------- K5: output rows ----------------
__global__ void k_out(float* __restrict__ out) {
    int i = blockIdx.x;
    float si = g_s[i];
    float target = -si;
    int lo = 0, hi = NN;
    while (lo < hi) {
        int mid = (lo + hi) >> 1;
        if (g_sorted[mid] < target) lo = mid + 1; else hi = mid;
    }
    int k = lo;
    float D = decode_D();
    float m = si + D;
    if (m < 0.f) m *= 0.01f;
    double c1 = exp((double)si + (double)D - (double)m);
    double c2 = exp(0.01 * (double)si - (double)m);
    double zsuf = (double)g_zp1[NN] - (double)g_zp1[k];
    double Z = c1 * zsuf + c2 * (double)g_zp2[k];
    float f1 = (float)(c1 / Z);
    float f2 = (float)(c2 / Z);
    int t = threadIdx.x;
    const float4* P1k = (const float4*)(g_P1 + (size_t)k * DVV);
    const float4* P2k = (const float4*)(g_P2 + (size_t)k * DVV);
    const float4* T1  = (const float4*)(g_P1 + (size_t)NN * DVV);
    float4 p1 = P1k[t], p2 = P2k[t], t1 = T1[t];
    float4 o;
    o.x = f1 * (t1.x - p1.x) + f2 * p2.x;
    o.y = f1 * (t1.y - p1.y) + f2 * p2.y;
    o.z = f1 * (t1.z - p1.z) + f2 * p2.z;
    o.w = f1 * (t1.w - p1.w) + f2 * p2.w;
    ((float4*)out)[(size_t)i * (DVV / 4) + t] = o;
}

// ---------------- launch ----------------
extern "C" void kernel_launch(void* const* d_in, const int* in_sizes, int n_in,
                              void* d_out, int out_size) {
    (void)in_sizes; (void)n_in; (void)out_size;
    const float* x    = (const float*)d_in[0];
    const float* w_w  = (const float*)d_in[1];
    const float* w_b  = (const float*)d_in[2];
    const float* wv_w = (const float*)d_in[3];
    const float* wv_b = (const float*)d_in[4];
    const float* a    = (const float*)d_in[5];
    float* out = (float*)d_out;

    static int smem_set = 0;
    if (!smem_set) {
        cudaFuncSetAttribute(k_vgemm_mma, cudaFuncAttributeMaxDynamicSharedMemorySize,
                             SMEM_VG_BYTES);
        smem_set = 1;
    }

    k_prep<<<2, 256>>>(w_w, w_b, a);
    k_edot<<<NN / 8 + 256, 256>>>(x, wv_w);
    k_rank<<<dim3(NN / 1024, NN / 256), 256>>>();
    k_vgemm_mma<<<dim3(DVV / 256, NN / 128), 512, SMEM_VG_BYTES>>>(wv_b);
    k_scanlb<<<NCHUNK, 256>>>();
    k_out<<<NN, 128>>>(out);
}

// round 14
// speedup vs baseline: 1.1485x; 1.1485x over previous
#include <cuda_runtime.h>
#include <cuda_fp16.h>
#include <math.h>
#include <stdint.h>

#define NN    8192
#define DIMM  512
#define DKK   128
#define DVV   512
#define NCHUNK 256
#define CHUNK  32

// ---------------- scratch (device globals; no allocation) ----------------
__device__ float  g_u1[DIMM], g_u2[DIMM];
__device__ double g_beta[2];
__device__ float  g_s[NN], g_d[NN];
__device__ uint32_t g_Dbits;
__device__ int    g_rank[NN];
__device__ int    g_ord[NN];
__device__ unsigned long long g_key[NN];
__device__ float  g_sorted[NN];
__device__ float  g_w1[NN], g_w2[NN];
__device__ float  g_Vs[(size_t)NN * DVV];
__device__ float  g_P1[(size_t)(NN + 1) * DVV];
__device__ float  g_P2[(size_t)(NN + 1) * DVV];
__device__ float  g_zp1[NN + 1], g_zp2[NN + 1];
__device__ float  g_aggA1[(size_t)NCHUNK * DVV], g_aggA2[(size_t)NCHUNK * DVV];
__device__ float  g_incA1[(size_t)NCHUNK * DVV], g_incA2[(size_t)NCHUNK * DVV];
__device__ float  g_aggW[NCHUNK][2], g_incW[NCHUNK][2];
__device__ int    g_status[NCHUNK];
__device__ __half g_Xh[(size_t)NN * DIMM];
__device__ __half g_Wh[(size_t)DVV * DIMM];

// ---------------- helpers ----------------
__device__ __forceinline__ uint32_t smem_u32(const void* p) {
    uint32_t a;
    asm("{ .reg .u64 t; cvta.to.shared.u64 t, %1; cvt.u32.u64 %0, t; }" : "=r"(a) : "l"(p));
    return a;
}
__device__ __forceinline__ void cp16(uint32_t saddr, const void* gaddr) {
    asm volatile("cp.async.cg.shared.global [%0], [%1], 16;" :: "r"(saddr), "l"(gaddr) : "memory");
}
#define CP_COMMIT() asm volatile("cp.async.commit_group;" ::: "memory")
#define CP_WAIT(n)  asm volatile("cp.async.wait_group %0;" :: "n"(n) : "memory")

__device__ __forceinline__ void ldsm_x4(uint32_t& r0, uint32_t& r1, uint32_t& r2, uint32_t& r3,
                                        uint32_t addr) {
    asm volatile("ldmatrix.sync.aligned.m8n8.x4.shared.b16 {%0,%1,%2,%3}, [%4];"
                 : "=r"(r0), "=r"(r1), "=r"(r2), "=r"(r3) : "r"(addr));
}
__device__ __forceinline__ void mma16816(float* c, uint32_t a0, uint32_t a1, uint32_t a2,
                                         uint32_t a3, uint32_t b0, uint32_t b1) {
    asm volatile("mma.sync.aligned.m16n8k16.row.col.f32.f16.f16.f32 "
                 "{%0,%1,%2,%3}, {%4,%5,%6,%7}, {%8,%9}, {%0,%1,%2,%3};"
                 : "+f"(c[0]), "+f"(c[1]), "+f"(c[2]), "+f"(c[3])
                 : "r"(a0), "r"(a1), "r"(a2), "r"(a3), "r"(b0), "r"(b1));
}
__device__ __forceinline__ float decode_D() {
    uint32_t u = g_Dbits;
    uint32_t s = (u & 0x80000000u) ? (u ^ 0x80000000u) : ~u;
    return __uint_as_float(s);
}

// ---------------- K0: u1/u2, betas; resets (R8 version) ----------------
__global__ void k_prep(const float* __restrict__ Ww, const float* __restrict__ wb,
                       const float* __restrict__ a) {
    int d = blockIdx.x * 256 + threadIdx.x;
    double s1 = 0.0, s2 = 0.0;
    for (int k = 0; k < DKK; k++) {
        double w = Ww[(size_t)k * DIMM + d];
        s1 += w * (double)a[k];
        s2 += w * (double)a[DKK + k];
    }
    g_u1[d] = (float)s1;
    g_u2[d] = (float)s2;
    if (blockIdx.x == 0) g_status[threadIdx.x] = 0;
    if (d == 0) {
        double b1 = 0.0, b2 = 0.0;
        for (int k = 0; k < DKK; k++) {
            b1 += (double)wb[k] * (double)a[k];
            b2 += (double)wb[k] * (double)a[DKK + k];
        }
        g_beta[0] = b1; g_beta[1] = b2;
        g_Dbits = 0u;
    }
}

// ---------------- K1: e_src/e_dst + keys + max(d) + fp16 conversion (fused) -------
__global__ void k_edot(const float* __restrict__ X, const float* __restrict__ Wv) {
    if (blockIdx.x >= NN / 8) {
        int idx = (blockIdx.x - NN / 8) * 256 + threadIdx.x;
        float4 v = ((const float4*)Wv)[idx];
        __half2* pw = (__half2*)g_Wh;
        pw[idx * 2]     = __floats2half2_rn(v.x, v.y);
        pw[idx * 2 + 1] = __floats2half2_rn(v.z, v.w);
        return;
    }
    int warp = (blockIdx.x * blockDim.x + threadIdx.x) >> 5;
    int lane = threadIdx.x & 31;
    const float4* xr = (const float4*)(X + (size_t)warp * DIMM);
    const float4* u1 = (const float4*)g_u1;
    const float4* u2 = (const float4*)g_u2;
    __half2* dxh = (__half2*)(g_Xh + (size_t)warp * DIMM);
    float a1 = 0.f, a2 = 0.f;
#pragma unroll
    for (int i = 0; i < 4; i++) {
        int p = lane + 32 * i;
        float4 xv = xr[p], v1 = u1[p], v2 = u2[p];
        a1 += xv.x * v1.x + xv.y * v1.y + xv.z * v1.z + xv.w * v1.w;
        a2 += xv.x * v2.x + xv.y * v2.y + xv.z * v2.z + xv.w * v2.w;
        dxh[2 * p]     = __floats2half2_rn(xv.x, xv.y);
        dxh[2 * p + 1] = __floats2half2_rn(xv.z, xv.w);
    }
    for (int o = 16; o; o >>= 1) {
        a1 += __shfl_down_sync(0xffffffffu, a1, o);
        a2 += __shfl_down_sync(0xffffffffu, a2, o);
    }
    if (lane == 0) {
        float dv = (float)((double)a2 + g_beta[1]);
        g_s[warp] = (float)((double)a1 + g_beta[0]);
        g_d[warp] = dv;
        g_rank[warp] = 0;
        uint32_t u = __float_as_uint(dv);
        u ^= (uint32_t)(((int32_t)u >> 31)) | 0x80000000u;
        g_key[warp] = ((unsigned long long)u << 13) | (unsigned long long)warp;
        atomicMax(&g_Dbits, u);
    }
}

// ---------------- K2: ranks via u64 key compares (tile 256, 4 j/thread) ----------------
__global__ void k_rank() {
    __shared__ unsigned long long ks[256];
    int t = threadIdx.x;
    ks[t] = g_key[blockIdx.y * 256 + t];
    __syncthreads();
    int j0 = blockIdx.x * 1024 + t;
    unsigned long long k0 = g_key[j0], k1 = g_key[j0 + 256];
    unsigned long long k2 = g_key[j0 + 512], k3 = g_key[j0 + 768];
    int c0 = 0, c1 = 0, c2 = 0, c3 = 0;
#pragma unroll 8
    for (int i = 0; i < 256; i++) {
        unsigned long long kk = ks[i];
        c0 += (kk < k0); c1 += (kk < k1);
        c2 += (kk < k2); c3 += (kk < k3);
    }
    atomicAdd(&g_rank[j0], c0);
    atomicAdd(&g_rank[j0 + 256], c1);
    atomicAdd(&g_rank[j0 + 512], c2);
    atomicAdd(&g_rank[j0 + 768], c3);
}

// ---------------- K2b: scatter sorted d + weights + inverse permutation ----------
__global__ void k_scatterd() {
    int j = blockIdx.x * 256 + threadIdx.x;
    int r = g_rank[j];
    float dj = g_d[j];
    float D = decode_D();
    g_sorted[r] = dj;
    g_w1[r] = expf(dj - D);
    g_w2[r] = expf(0.01f * dj);
    g_ord[r] = j;
}

// ---------------- K3: warp-MMA V GEMM (fp16, 128x256, 3-stage, natural order) ----
#define KT 64
#define A_TILE (128 * 128)
#define B_TILE (256 * 128)
#define STAGE  (A_TILE + B_TILE)
#define SMEM_VG_BYTES (3 * STAGE)    // 144 KB

__device__ __forceinline__ uint32_t swz(uint32_t row, uint32_t colb) {
    return row * 128u + (colb ^ ((row & 7u) << 4));
}

__global__ void __launch_bounds__(512)
k_vgemm_mma(const float* __restrict__ bv) {
    extern __shared__ char smem[];
    uint32_t sb = smem_u32(smem);
    const int tid = threadIdx.x;
    const int wid = tid >> 5, lane = tid & 31;
    const int wm = wid & 3, wn = wid >> 2;
    const int m0 = blockIdx.y * 128, n0 = blockIdx.x * 256;

    const uint32_t sA[3] = { sb, sb + STAGE, sb + 2 * STAGE };
    const uint32_t sB[3] = { sb + A_TILE, sb + STAGE + A_TILE, sb + 2 * STAGE + A_TILE };

    float acc[2][8][4];
#pragma unroll
    for (int i = 0; i < 2; i++)
#pragma unroll
        for (int j = 0; j < 8; j++)
#pragma unroll
            for (int q = 0; q < 4; q++) acc[i][j][q] = 0.f;

    const int arow = tid >> 2, ach0 = (tid & 3) * 2;
    const int brow = tid >> 1, bch0 = (tid & 1) * 4;

    auto issue = [&](int it, int buf) {
        int k0 = it * KT;
        const __half* ga = g_Xh + (size_t)(m0 + arow) * DIMM + k0;
        const __half* gb = g_Wh + (size_t)(n0 + brow) * DIMM + k0;
#pragma unroll
        for (int c = 0; c < 2; c++) {
            int ch = ach0 + c;
            cp16(sA[buf] + swz(arow, ch * 16), ga + ch * 8);
        }
#pragma unroll
        for (int c = 0; c < 4; c++) {
            int ch = bch0 + c;
            cp16(sB[buf] + swz(brow, ch * 16), gb + ch * 8);
        }
    };

    issue(0, 0); CP_COMMIT();
    issue(1, 1); CP_COMMIT();

    int buf = 0;
    for (int it = 0; it < 8; it++) {
        if (it < 7) { CP_WAIT(1); } else { CP_WAIT(0); }
        __syncthreads();

#pragma unroll
        for (int ks = 0; ks < 4; ks++) {
            uint32_t colb = ks * 32 + ((lane >> 4) << 4);
            uint32_t af[2][4];
#pragma unroll
            for (int mt = 0; mt < 2; mt++) {
                uint32_t row = wm * 32 + mt * 16 + (lane & 15);
                ldsm_x4(af[mt][0], af[mt][1], af[mt][2], af[mt][3], sA[buf] + swz(row, colb));
            }
            uint32_t bf[4][4];
#pragma unroll
            for (int np = 0; np < 4; np++) {
                uint32_t row = wn * 64 + np * 16 + (lane & 15);
                ldsm_x4(bf[np][0], bf[np][1], bf[np][2], bf[np][3], sB[buf] + swz(row, colb));
            }
#pragma unroll
            for (int mt = 0; mt < 2; mt++)
#pragma unroll
                for (int nt = 0; nt < 8; nt++) {
                    int np = nt >> 1, sel = nt & 1;
                    mma16816(acc[mt][nt], af[mt][0], af[mt][1], af[mt][2], af[mt][3],
                             bf[np][0 + sel], bf[np][2 + sel]);
                }
        }

        if (it < 6) {
            issue(it + 2, (it + 2) % 3);
            CP_COMMIT();
        }
        buf = (buf + 1) % 3;
    }

    // epilogue: bias + NATURAL-order row stores (no rank dependency)
    const int g = lane >> 2, tg = lane & 3;
#pragma unroll
    for (int mt = 0; mt < 2; mt++) {
        int j0 = m0 + wm * 32 + mt * 16 + g;
        int j1 = j0 + 8;
        float* d0 = g_Vs + (size_t)j0 * DVV;
        float* d1 = g_Vs + (size_t)j1 * DVV;
#pragma unroll
        for (int nt = 0; nt < 8; nt++) {
            int col = n0 + wn * 64 + nt * 8 + 2 * tg;
            float2 bb = *(const float2*)(bv + col);
            float2 o0 = make_float2(acc[mt][nt][0] + bb.x, acc[mt][nt][1] + bb.y);
            float2 o1 = make_float2(acc[mt][nt][2] + bb.x, acc[mt][nt][3] + bb.y);
            *(float2*)(d0 + col) = o0;
            *(float2*)(d1 + col) = o1;
        }
    }
}

// ---------------- K4: decoupled-lookback scan (R8) with permutation gather -------
__global__ void __launch_bounds__(256)
k_scanlb() {
    __shared__ int s_p, s_type;
    __shared__ float s_excw1, s_excw2;
    __shared__ float sw1a[CHUNK], sw2a[CHUNK];
    __shared__ int sord[CHUNK];
    int c = blockIdx.x, t = threadIdx.x;
    int r0 = c * CHUNK;
    int col = 2 * t;

    if (t < CHUNK) {
        sw1a[t] = g_w1[r0 + t];
        sw2a[t] = g_w2[r0 + t];
        sord[t] = g_ord[r0 + t];
    }
    if (t == 0) { s_excw1 = 0.f; s_excw2 = 0.f; }
    __syncthreads();

    float2 vv[CHUNK];
    float2 a1 = make_float2(0.f, 0.f), a2 = make_float2(0.f, 0.f);
#pragma unroll 4
    for (int r = 0; r < CHUNK; r++) {
        float w1 = sw1a[r], w2 = sw2a[r];
        float2 v = *(const float2*)(g_Vs + (size_t)sord[r] * DVV + col);
        vv[r] = v;
        a1.x += w1 * v.x; a1.y += w1 * v.y;
        a2.x += w2 * v.x; a2.y += w2 * v.y;
    }
    *(float2*)(g_aggA1 + (size_t)c * DVV + col) = a1;
    *(float2*)(g_aggA2 + (size_t)c * DVV + col) = a2;
    float lw1 = 0.f, lw2 = 0.f;
    if (t == 0) {
        for (int r = 0; r < CHUNK; r++) { lw1 += sw1a[r]; lw2 += sw2a[r]; }
        g_aggW[c][0] = lw1; g_aggW[c][1] = lw2;
    }
    __threadfence();
    __syncthreads();
    if (t == 0) atomicExch(&g_status[c], 1);

    float2 e1 = make_float2(0.f, 0.f), e2 = make_float2(0.f, 0.f);
    if (c > 0) {
        int p = c - 1;
        while (true) {
            if (t == 0) {
                int st;
                do { st = atomicAdd(&g_status[p], 0); } while (st == 0);
                s_type = st; s_p = p;
            }
            __syncthreads();
            int type = s_type, pp = s_p;
            __threadfence();
            const float* b1 = (type == 2 ? g_incA1 : g_aggA1) + (size_t)pp * DVV;
            const float* b2 = (type == 2 ? g_incA2 : g_aggA2) + (size_t)pp * DVV;
            float2 x1 = *(const float2*)(b1 + col);
            float2 x2 = *(const float2*)(b2 + col);
            e1.x += x1.x; e1.y += x1.y;
            e2.x += x2.x; e2.y += x2.y;
            if (t == 0) {
                const float* w = (type == 2 ? g_incW[pp] : g_aggW[pp]);
                s_excw1 += w[0]; s_excw2 += w[1];
            }
            if (type == 2 || pp == 0) break;
            p = pp - 1;
            __syncthreads();
        }
    }
    __syncthreads();

    *(float2*)(g_incA1 + (size_t)c * DVV + col) = make_float2(e1.x + a1.x, e1.y + a1.y);
    *(float2*)(g_incA2 + (size_t)c * DVV + col) = make_float2(e2.x + a2.x, e2.y + a2.y);
    if (t == 0) {
        g_incW[c][0] = s_excw1 + lw1;
        g_incW[c][1] = s_excw2 + lw2;
    }
    __threadfence();
    __syncthreads();
    if (t == 0) atomicExch(&g_status[c], 2);

    float2 run1 = e1, run2 = e2;
#pragma unroll 4
    for (int r = 0; r < CHUNK; r++) {
        *(float2*)(g_P1 + (size_t)(r0 + r) * DVV + col) = run1;
        *(float2*)(g_P2 + (size_t)(r0 + r) * DVV + col) = run2;
        float w1 = sw1a[r], w2 = sw2a[r];
        float2 v = vv[r];
        run1.x += w1 * v.x; run1.y += w1 * v.y;
        run2.x += w2 * v.x; run2.y += w2 * v.y;
    }
    if (c == NCHUNK - 1) {
        *(float2*)(g_P1 + (size_t)NN * DVV + col) = run1;
        *(float2*)(g_P2 + (size_t)NN * DVV + col) = run2;
    }
    if (t == 0) {
        float z1 = s_excw1, z2 = s_excw2;
        for (int r = 0; r < CHUNK; r++) {
            g_zp1[r0 + r] = z1; g_zp2[r0 + r] = z2;
            z1 += sw1a[r]; z2 += sw2a[r];
        }
        if (c == NCHUNK - 1) { g_zp1[NN] = z1; g_zp2[NN] = z2; }
    }
}

// ---------------- K5: output rows ----------------
__global__ void k_out(float* __restrict__ out) {
    int i = blockIdx.x;
    float si = g_s[i];
    float target = -si;
    int lo = 0, hi = NN;
    while (lo < hi) {
        int mid = (lo + hi) >> 1;
        if (g_sorted[mid] < target) lo = mid + 1; else hi = mid;
    }
    int k = lo;
    float D = decode_D();
    float m = si + D;
    if (m < 0.f) m *= 0.01f;
    double c1 = exp((double)si + (double)D - (double)m);
    double c2 = exp(0.01 * (double)si - (double)m);
    double zsuf = (double)g_zp1[NN] - (double)g_zp1[k];
    double Z = c1 * zsuf + c2 * (double)g_zp2[k];
    float f1 = (float)(c1 / Z);
    float f2 = (float)(c2 / Z);
    int t = threadIdx.x;
    const float4* P1k = (const float4*)(g_P1 + (size_t)k * DVV);
    const float4* P2k = (const float4*)(g_P2 + (size_t)k * DVV);
    const float4* T1  = (const float4*)(g_P1 + (size_t)NN * DVV);
    float4 p1 = P1k[t], p2 = P2k[t], t1 = T1[t];
    float4 o;
    o.x = f1 * (t1.x - p1.x) + f2 * p2.x;
    o.y = f1 * (t1.y - p1.y) + f2 * p2.y;
    o.z = f1 * (t1.z - p1.z) + f2 * p2.z;
    o.w = f1 * (t1.w - p1.w) + f2 * p2.w;
    ((float4*)out)[(size_t)i * (DVV / 4) + t] = o;
}

// ---------------- stream/event setup (static init: before harness checkpoints) ---
struct SideStream {
    cudaStream_t s2 = nullptr;
    cudaEvent_t ev1 = nullptr, ev2 = nullptr;
    SideStream() {
        cudaStreamCreateWithFlags(&s2, cudaStreamNonBlocking);
        cudaEventCreateWithFlags(&ev1, cudaEventDisableTiming);
        cudaEventCreateWithFlags(&ev2, cudaEventDisableTiming);
    }
};
static SideStream g_ss;

// ---------------- launch ----------------
extern "C" void kernel_launch(void* const* d_in, const int* in_sizes, int n_in,
                              void* d_out, int out_size) {
    (void)in_sizes; (void)n_in; (void)out_size;
    const float* x    = (const float*)d_in[0];
    const float* w_w  = (const float*)d_in[1];
    const float* w_b  = (const float*)d_in[2];
    const float* wv_w = (const float*)d_in[3];
    const float* wv_b = (const float*)d_in[4];
    const float* a    = (const float*)d_in[5];
    float* out = (float*)d_out;

    static int smem_set = 0;
    if (!smem_set) {
        cudaFuncSetAttribute(k_vgemm_mma, cudaFuncAttributeMaxDynamicSharedMemorySize,
                             SMEM_VG_BYTES);
        smem_set = 1;
    }

    k_prep<<<2, 256>>>(w_w, w_b, a);
    k_edot<<<NN / 8 + 256, 256>>>(x, wv_w);

    // fork: rank + scatterd on side stream, concurrent with vgemm
    cudaEventRecord(g_ss.ev1, 0);
    cudaStreamWaitEvent(g_ss.s2, g_ss.ev1, 0);
    k_rank<<<dim3(NN / 1024, NN / 256), 256, 0, g_ss.s2>>>();
    k_scatterd<<<NN / 256, 256, 0, g_ss.s2>>>();
    cudaEventRecord(g_ss.ev2, g_ss.s2);

    k_vgemm_mma<<<dim3(DVV / 256, NN / 128), 512, SMEM_VG_BYTES>>>(wv_b);

    // join
    cudaStreamWaitEvent(0, g_ss.ev2, 0);
    k_scanlb<<<NCHUNK, 256>>>();
    k_out<<<NN, 128>>>(out);
}